// round 15
// baseline (speedup 1.0000x reference)
#include <cuda_runtime.h>
#include <cuda_bf16.h>
#include <math.h>

// Problem constants
#define B_   8
#define C_   8
#define K_   10
#define D_   512
#define H_   96
#define W_   96
#define HW_  (H_*W_)          // 9216
#define NPIX (B_*HW_)         // 73728
#define DS_  4                // d splits
#define DPS_ 128              // d per split
#define SEGS 24               // k2 segments (4 rows each)

// ---------------- scratch (__device__ globals; no allocations) ----------------
// prototypes in d-pair packed layout: g_P2[d2][c*28 + k*2 + parity]
__device__ __align__(16) float g_P2[256 * 224];                     // 229 KB
__device__ __align__(16) float g_part[(size_t)DS_ * NPIX * 12];     // 14.2 MB partial dots
__device__ __align__(16) float g_NumH[(size_t)B_*C_*H_*W_*12];      // 28.3 MB
__device__ float g_Mom[64 * 66];                                    // per-bc moments (atomic)
__device__ int   g_cnt[64];                                         // class pixel counts per (b,c)

__constant__ int cPK[45] = {0,0,0,0,0,0,0,0,0, 1,1,1,1,1,1,1,1, 2,2,2,2,2,2,2,
                            3,3,3,3,3,3, 4,4,4,4,4, 5,5,5,5, 6,6,6, 7,7, 8};
__constant__ int cPL[45] = {1,2,3,4,5,6,7,8,9, 2,3,4,5,6,7,8,9, 3,4,5,6,7,8,9,
                            4,5,6,7,8,9, 5,6,7,8,9, 6,7,8,9, 7,8,9, 8,9, 9};

// ---- f32x2 packed helpers ----
__device__ __forceinline__ unsigned long long pk2(float a, float b) {
    unsigned long long r;
    asm("mov.b64 %0, {%1, %2};" : "=l"(r) : "f"(a), "f"(b));
    return r;
}
__device__ __forceinline__ void ffma2(unsigned long long& d, unsigned long long a, unsigned long long b) {
    asm("fma.rn.f32x2 %0, %1, %2, %0;" : "+l"(d) : "l"(a), "l"(b));
}
__device__ __forceinline__ float upsum(unsigned long long v) {
    float lo, hi;
    asm("mov.b64 {%0, %1}, %2;" : "=f"(lo), "=f"(hi) : "l"(v));
    return lo + hi;
}

// ---------------- k0: normalize prototypes into packed pair layout + zero scratch ----------------
__global__ void k0_norm_proto(const float* __restrict__ P) {
    int blk = blockIdx.x;
    int tid = threadIdx.x;          // 128
    if (blk == 80) {                // zero replay-state scratch
        for (int i = tid; i < 64 * 66; i += 128) g_Mom[i] = 0.f;
        if (tid < 64) g_cnt[tid] = 0;
        return;
    }
    const float* row = P + blk * D_;
    float ss = 0.f;
    for (int i = tid; i < D_; i += 128) { float v = row[i]; ss = fmaf(v, v, ss); }
    #pragma unroll
    for (int o = 16; o; o >>= 1) ss += __shfl_xor_sync(0xffffffffu, ss, o);
    __shared__ float red[4];
    if ((tid & 31) == 0) red[tid >> 5] = ss;
    __syncthreads();
    float tot = red[0] + red[1] + red[2] + red[3];
    float inv = 1.0f / fmaxf(sqrtf(tot), 1e-12f);
    int c = blk / K_, k = blk % K_;
    for (int d = tid; d < D_; d += 128)
        g_P2[(d >> 1) * 224 + c * 28 + k * 2 + (d & 1)] = row[d] * inv;
}

// ---------------- k1: partial sims over a 128-d slice (FFMA2 packed) ----------------
// grid = 1024: blk = ds*256 + (b*32 + rowtriple); block = 288 threads = 3 rows.
// __launch_bounds__(288, 4): cap regs at 56 -> 4 blocks/SM.
__global__ __launch_bounds__(288, 4) void k1_sim(const float* __restrict__ F,
                                                 const int* __restrict__ mask) {
    __shared__ __align__(16) float sp[32 * 224];   // 28 KB: 32 d2-rows of packed protos

    int tid = threadIdx.x;
    int blk = blockIdx.x;
    int ds  = blk >> 8;
    int sub = blk & 255;
    int b = sub >> 5;
    int row0 = (sub & 31) * 3;
    int pin  = row0 * W_ + tid;
    int pixg = b * HW_ + pin;

    int m = mask[pixg];
    int c = (m > 0) ? (m - 1) : 0;

    const float* fb = F + ((size_t)b * D_ + ds * DPS_) * HW_ + pin;

    unsigned long long n2 = 0ull;
    unsigned long long s2[10];
    #pragma unroll
    for (int k = 0; k < 10; k++) s2[k] = 0ull;

    for (int ch = 0; ch < 2; ch++) {
        __syncthreads();
        const float4* src = (const float4*)(g_P2 + (size_t)(ds * 64 + ch * 32) * 224);
        float4* dst = (float4*)sp;
        for (int i = tid; i < 32 * 224 / 4; i += 288) dst[i] = src[i];
        __syncthreads();

        const float* fp = fb + (size_t)ch * 64 * HW_;
        #pragma unroll 2
        for (int i2 = 0; i2 < 32; i2 += 4) {
            float f[8];
            #pragma unroll
            for (int j = 0; j < 8; j++) f[j] = fp[(size_t)(i2 * 2 + j) * HW_];
            #pragma unroll
            for (int j2 = 0; j2 < 4; j2++) {
                unsigned long long f2 = pk2(f[2 * j2], f[2 * j2 + 1]);
                const ulonglong2* q = (const ulonglong2*)(sp + (i2 + j2) * 224 + c * 28);
                ulonglong2 q0 = q[0], q1 = q[1], q2 = q[2], q3 = q[3], q4 = q[4];
                ffma2(n2, f2, f2);
                ffma2(s2[0], f2, q0.x); ffma2(s2[1], f2, q0.y);
                ffma2(s2[2], f2, q1.x); ffma2(s2[3], f2, q1.y);
                ffma2(s2[4], f2, q2.x); ffma2(s2[5], f2, q2.y);
                ffma2(s2[6], f2, q3.x); ffma2(s2[7], f2, q3.y);
                ffma2(s2[8], f2, q4.x); ffma2(s2[9], f2, q4.y);
            }
        }
    }
    float4* o = (float4*)(g_part + ((size_t)ds * NPIX + pixg) * 12);
    o[0] = make_float4(upsum(s2[0]), upsum(s2[1]), upsum(s2[2]), upsum(s2[3]));
    o[1] = make_float4(upsum(s2[4]), upsum(s2[5]), upsum(s2[6]), upsum(s2[7]));
    o[2] = make_float4(upsum(s2[8]), upsum(s2[9]), upsum(n2), 0.f);
}

// ---------------- k1b: merge partials + normalize + horizontal 7-tap pool ----------------
// grid = 768 (b,h); block = 96 threads (one per w).
__global__ __launch_bounds__(96) void k1b(const int* __restrict__ mask) {
    __shared__ __align__(16) float sS[96 * 12];
    __shared__ int smask[96];
    __shared__ int hist[8];

    int bh = blockIdx.x;
    int b = bh / H_, h = bh - b * H_;
    int w = threadIdx.x;
    int pixg = b * HW_ + h * W_ + w;

    if (w < 8) hist[w] = 0;
    int m = mask[pixg];
    smask[w] = m;
    __syncthreads();
    if (m > 0) atomicAdd(&hist[m - 1], 1);

    float a[11];
    #pragma unroll
    for (int i = 0; i < 11; i++) a[i] = 0.f;
    #pragma unroll
    for (int ds = 0; ds < DS_; ds++) {
        const float4* p = (const float4*)(g_part + ((size_t)ds * NPIX + pixg) * 12);
        float4 x = p[0], y = p[1], z = p[2];
        a[0]+=x.x; a[1]+=x.y; a[2]+=x.z; a[3]+=x.w;
        a[4]+=y.x; a[5]+=y.y; a[6]+=y.z; a[7]+=y.w;
        a[8]+=z.x; a[9]+=z.y; a[10]+=z.z;
    }
    float inv = 1.0f / fmaxf(sqrtf(a[10]), 1e-12f);
    float* so = sS + w * 12;
    #pragma unroll
    for (int k = 0; k < 10; k++) so[k] = a[k] * inv;
    so[10] = 0.f; so[11] = 0.f;
    __syncthreads();

    // horizontal 7-tap class-scattered pool
    #pragma unroll
    for (int cc = 0; cc < 8; cc++) {
        float s[11];
        #pragma unroll
        for (int i = 0; i < 11; i++) s[i] = 0.f;
        #pragma unroll
        for (int dw = -3; dw <= 3; dw++) {
            int ww = w + dw;
            if ((unsigned)ww < 96u && smask[ww] == cc + 1) {
                const float4* sv = (const float4*)(sS + (size_t)ww * 12);
                float4 x = sv[0], y = sv[1], z = sv[2];
                s[0]+=x.x; s[1]+=x.y; s[2]+=x.z; s[3]+=x.w;
                s[4]+=y.x; s[5]+=y.y; s[6]+=y.z; s[7]+=y.w;
                s[8]+=z.x; s[9]+=z.y; s[10]+=1.f;
            }
        }
        float4* o = (float4*)(g_NumH + (size_t)(((b * 8 + cc) * H_ + h) * W_ + w) * 12);
        o[0] = make_float4(s[0], s[1], s[2], s[3]);
        o[1] = make_float4(s[4], s[5], s[6], s[7]);
        o[2] = make_float4(s[8], s[9], s[10], 0.f);
    }
    if (w < 8) atomicAdd(&g_cnt[b * 8 + w], hist[w]);
}

// ---------------- k2b: sliding vertical 7-tap + region + atomic per-bc moments ----------------
// grid = 64*SEGS: (bc, seg of 4 rows); block = 96 threads (one per w).
__global__ __launch_bounds__(96) void k2b() {
    int bc  = blockIdx.x / SEGS;
    int seg = blockIdx.x - bc * SEGS;
    int w = threadIdx.x;

    const float* base = g_NumH + (size_t)bc * HW_ * 12 + (size_t)w * 12;

    float vs[11];
    #pragma unroll
    for (int i = 0; i < 11; i++) vs[i] = 0.f;

    auto acc = [&](int hh, float sg) {
        const float4* rr = (const float4*)(base + (size_t)hh * (W_ * 12));
        float4 x = rr[0], y = rr[1], z = rr[2];
        vs[0] = fmaf(sg, x.x, vs[0]); vs[1] = fmaf(sg, x.y, vs[1]);
        vs[2] = fmaf(sg, x.z, vs[2]); vs[3] = fmaf(sg, x.w, vs[3]);
        vs[4] = fmaf(sg, y.x, vs[4]); vs[5] = fmaf(sg, y.y, vs[5]);
        vs[6] = fmaf(sg, y.z, vs[6]); vs[7] = fmaf(sg, y.w, vs[7]);
        vs[8] = fmaf(sg, z.x, vs[8]); vs[9] = fmaf(sg, z.y, vs[9]);
        vs[10] = fmaf(sg, z.z, vs[10]);
    };

    int h0 = seg * 4;
    #pragma unroll
    for (int hh = h0 - 3; hh < h0 + 3; hh++)
        if (hh >= 0) acc(hh, 1.f);

    float V = 0.f;
    float Sr[10]; float M[55];
    #pragma unroll
    for (int k = 0; k < 10; k++) Sr[k] = 0.f;
    #pragma unroll
    for (int i = 0; i < 55; i++) M[i] = 0.f;

    #pragma unroll
    for (int h = h0; h < h0 + 4; h++) {
        if (h + 3 < 96) acc(h + 3, 1.f);
        float den = vs[10] * (1.0f / 49.0f);
        if (den > 0.05f) {
            float inv = 1.0f / (den + 1e-8f);
            float r[10];
            #pragma unroll
            for (int k = 0; k < 10; k++) r[k] = (vs[k] * (1.0f / 49.0f)) * inv;
            V += 1.f;
            #pragma unroll
            for (int k = 0; k < 10; k++) Sr[k] += r[k];
            int idx = 0;
            #pragma unroll
            for (int k = 0; k < 10; k++)
                #pragma unroll
                for (int l = k; l < 10; l++) { M[idx] = fmaf(r[k], r[l], M[idx]); idx++; }
        }
        if (h - 3 >= 0) acc(h - 3, -1.f);
    }

    // warp butterfly reduce (3 warps, same (bc,seg))
    #pragma unroll
    for (int o = 16; o; o >>= 1) V += __shfl_xor_sync(0xffffffffu, V, o);
    #pragma unroll
    for (int k = 0; k < 10; k++) {
        float v = Sr[k];
        #pragma unroll
        for (int o = 16; o; o >>= 1) v += __shfl_xor_sync(0xffffffffu, v, o);
        Sr[k] = v;
    }
    #pragma unroll
    for (int i = 0; i < 55; i++) {
        float v = M[i];
        #pragma unroll
        for (int o = 16; o; o >>= 1) v += __shfl_xor_sync(0xffffffffu, v, o);
        M[i] = v;
    }
    __shared__ float red[3][66];
    int lane = w & 31, wid = w >> 5;
    if (lane == 0) {
        red[wid][0] = V;
        #pragma unroll
        for (int k = 0; k < 10; k++) red[wid][1 + k] = Sr[k];
        #pragma unroll
        for (int i = 0; i < 55; i++) red[wid][11 + i] = M[i];
    }
    __syncthreads();
    if (w < 66) {
        float s = red[0][w] + red[1][w] + red[2][w];
        atomicAdd(&g_Mom[bc * 66 + w], s);
    }
}

// ---------------- k3: finalize scalar (1 block, 32 warps; warp per 2 bc) ----------------
__global__ __launch_bounds__(1024) void k3(float* __restrict__ out) {
    __shared__ float sM[64][66];
    __shared__ float sla[64], saf[64];
    int tid = threadIdx.x;
    int wi = tid >> 5, lane = tid & 31;

    #pragma unroll
    for (int t = wi * 2; t < wi * 2 + 2; t++) {
        for (int i = lane; i < 66; i += 32) sM[t][i] = g_Mom[t * 66 + i];
        __syncwarp();
        const float* mm = sM[t];
        float V = mm[0];
        float Vf = fmaxf(V, 1.0f);
        float invVf = 1.0f / Vf;

        float Srk = 0.f, nk = 0.f;
        if (lane < 10) {
            Srk = mm[1 + lane];
            int di = 10 * lane - lane * (lane - 1) / 2;
            float cv = mm[11 + di] - Srk * Srk * invVf;
            nk = sqrtf(fmaxf(cv, 0.f));
        }
        float Sr[10], n[10];
        #pragma unroll
        for (int k = 0; k < 10; k++) {
            Sr[k] = __shfl_sync(0xffffffffu, Srk, k);
            n[k]  = __shfl_sync(0xffffffffu, nk, k);
        }
        float acci = 0.f;
        #pragma unroll
        for (int rep = 0; rep < 2; rep++) {
            int p = lane + rep * 32;
            if (p < 45) {
                int k = cPK[p], l = cPL[p];
                int idx = 10 * k - k * (k - 1) / 2 + (l - k);
                float cv = mm[11 + idx] - Sr[k] * Sr[l] * invVf;
                float g = cv / ((n[k] + 1e-8f) * (n[l] + 1e-8f)) * invVf;
                acci += 2.0f * g * g;
            }
        }
        #pragma unroll
        for (int o = 16; o; o >>= 1) acci += __shfl_xor_sync(0xffffffffu, acci, o);
        if (lane == 0) {
            float loss = acci * (1.0f / 90.0f);
            int cc = g_cnt[t];
            float act = (cc >= 1 && V >= 2.0f) ? 1.0f : 0.0f;
            sla[t] = loss * act;
            saf[t] = act;
        }
        __syncwarp();
    }
    __syncthreads();
    if (tid == 0) {
        float s = 0.f;
        #pragma unroll
        for (int b = 0; b < 8; b++) {
            float la = 0.f, af = 0.f;
            #pragma unroll
            for (int c = 0; c < 8; c++) { la += sla[b * 8 + c]; af += saf[b * 8 + c]; }
            s += la / fmaxf(af, 1.0f);
        }
        out[0] = s * 0.125f;
    }
}

// ---------------- launch ----------------
extern "C" void kernel_launch(void* const* d_in, const int* in_sizes, int n_in,
                              void* d_out, int out_size) {
    const float* F  = (const float*)d_in[0];   // feature_map [8,512,96,96]
    const float* P  = (const float*)d_in[1];   // prototypes  [80,512]
    const int*   Mk = (const int*)d_in[2];     // pseudo_mask [8,96,96]
    float* out = (float*)d_out;

    k0_norm_proto<<<81, 128>>>(P);    // #0 (includes scratch zeroing)
    k1_sim<<<1024, 288>>>(F, Mk);     // #1
    k1b<<<768, 96>>>(Mk);             // #2
    k2b<<<64 * SEGS, 96>>>();         // #3  <-- profiled: predict ~11us, occ ~40%
    k3<<<1, 1024>>>(out);             // #4
}